// round 3
// baseline (speedup 1.0000x reference)
#include <cuda_runtime.h>
#include <cuda_bf16.h>
#include <cstdint>

// Problem constants (fixed shapes for this problem instance)
#define NROWS 8192
#define FDIM  512

// Scratch: S = A @ X (16 MB), colsum (deg), rowsum (nonzeros per row)
__device__ float g_S[(size_t)NROWS * FDIM];
__device__ float g_deg[NROWS];      // column sums of binarized A
__device__ float g_rowcnt[NROWS];   // row sums of binarized A

// ---------------------------------------------------------------------------
// Kernel 0: zero deg (graph replays must redo this every launch)
// ---------------------------------------------------------------------------
__global__ void zero_deg_kernel() {
    int i = blockIdx.x * blockDim.x + threadIdx.x;
    if (i < NROWS) g_deg[i] = 0.0f;
}

// ---------------------------------------------------------------------------
// Kernel 1: one CTA (512 thr) per output row r.
//   Phase A: scan adj row r; each thread owns a CONTIGUOUS 16-element chunk
//            (4 float4). Count nonzeros, block-wide exclusive scan, then write
//            indices into s_idx in globally sorted order (deterministic).
//            atomicAdd(+1) into g_deg[col] per nonzero (exact integer adds,
//            order-independent). rowcnt = total nonzeros -> g_rowcnt[r].
//   Phase B: thread tid owns feature f=tid; S[r][f] = sum over sorted list.
// ---------------------------------------------------------------------------
__global__ __launch_bounds__(512) void spmm_ax_kernel(
    const float* __restrict__ adj,
    const float* __restrict__ X)
{
    __shared__ int s_idx[NROWS];     // 32 KB worst case
    __shared__ int s_warp[16];       // per-warp count totals
    __shared__ int s_total;

    const int r = blockIdx.x;
    const int tid = threadIdx.x;
    const int lane = tid & 31;
    const int wid = tid >> 5;

    // Phase A: each thread reads 4 consecutive float4 (64B contiguous)
    const float4* row4 = reinterpret_cast<const float4*>(adj + (size_t)r * NROWS);
    float4 v0 = row4[tid * 4 + 0];
    float4 v1 = row4[tid * 4 + 1];
    float4 v2 = row4[tid * 4 + 2];
    float4 v3 = row4[tid * 4 + 3];

    int c = 0;
    c += (v0.x != 0.0f) + (v0.y != 0.0f) + (v0.z != 0.0f) + (v0.w != 0.0f);
    c += (v1.x != 0.0f) + (v1.y != 0.0f) + (v1.z != 0.0f) + (v1.w != 0.0f);
    c += (v2.x != 0.0f) + (v2.y != 0.0f) + (v2.z != 0.0f) + (v2.w != 0.0f);
    c += (v3.x != 0.0f) + (v3.y != 0.0f) + (v3.z != 0.0f) + (v3.w != 0.0f);

    // Warp-level inclusive scan of counts
    int incl = c;
#pragma unroll
    for (int d = 1; d < 32; d <<= 1) {
        int t = __shfl_up_sync(0xFFFFFFFFu, incl, d);
        if (lane >= d) incl += t;
    }
    if (lane == 31) s_warp[wid] = incl;
    __syncthreads();
    if (wid == 0) {
        int wv = (lane < 16) ? s_warp[lane] : 0;
#pragma unroll
        for (int d = 1; d < 16; d <<= 1) {
            int t = __shfl_up_sync(0xFFFFFFFFu, wv, d);
            if (lane >= d) wv += t;
        }
        if (lane < 16) s_warp[lane] = wv;
        if (lane == 15) s_total = wv;
    }
    __syncthreads();

    int ofs = incl - c + (wid > 0 ? s_warp[wid - 1] : 0);

    // Write indices (sorted order since chunks are thread-contiguous),
    // and accumulate column sums.
    {
        int p = ofs;
        int base = tid * 16;
        if (v0.x != 0.0f) { s_idx[p++] = base + 0;  atomicAdd(&g_deg[base + 0], 1.0f); }
        if (v0.y != 0.0f) { s_idx[p++] = base + 1;  atomicAdd(&g_deg[base + 1], 1.0f); }
        if (v0.z != 0.0f) { s_idx[p++] = base + 2;  atomicAdd(&g_deg[base + 2], 1.0f); }
        if (v0.w != 0.0f) { s_idx[p++] = base + 3;  atomicAdd(&g_deg[base + 3], 1.0f); }
        if (v1.x != 0.0f) { s_idx[p++] = base + 4;  atomicAdd(&g_deg[base + 4], 1.0f); }
        if (v1.y != 0.0f) { s_idx[p++] = base + 5;  atomicAdd(&g_deg[base + 5], 1.0f); }
        if (v1.z != 0.0f) { s_idx[p++] = base + 6;  atomicAdd(&g_deg[base + 6], 1.0f); }
        if (v1.w != 0.0f) { s_idx[p++] = base + 7;  atomicAdd(&g_deg[base + 7], 1.0f); }
        if (v2.x != 0.0f) { s_idx[p++] = base + 8;  atomicAdd(&g_deg[base + 8], 1.0f); }
        if (v2.y != 0.0f) { s_idx[p++] = base + 9;  atomicAdd(&g_deg[base + 9], 1.0f); }
        if (v2.z != 0.0f) { s_idx[p++] = base + 10; atomicAdd(&g_deg[base + 10], 1.0f); }
        if (v2.w != 0.0f) { s_idx[p++] = base + 11; atomicAdd(&g_deg[base + 11], 1.0f); }
        if (v3.x != 0.0f) { s_idx[p++] = base + 12; atomicAdd(&g_deg[base + 12], 1.0f); }
        if (v3.y != 0.0f) { s_idx[p++] = base + 13; atomicAdd(&g_deg[base + 13], 1.0f); }
        if (v3.z != 0.0f) { s_idx[p++] = base + 14; atomicAdd(&g_deg[base + 14], 1.0f); }
        if (v3.w != 0.0f) { s_idx[p++] = base + 15; atomicAdd(&g_deg[base + 15], 1.0f); }
    }
    if (tid == 0) g_rowcnt[r] = 0.0f;   // placeholder; set below after total known
    __syncthreads();

    const int n = s_total;
    if (tid == 0) g_rowcnt[r] = (float)n;

    // Phase B: gather-accumulate in fixed (sorted) order.
    const int f = tid;
    float a0 = 0.f, a1 = 0.f, a2 = 0.f, a3 = 0.f;
    int t = 0;
    for (; t + 4 <= n; t += 4) {
        int j0 = s_idx[t + 0];
        int j1 = s_idx[t + 1];
        int j2 = s_idx[t + 2];
        int j3 = s_idx[t + 3];
        a0 += X[(size_t)j0 * FDIM + f];
        a1 += X[(size_t)j1 * FDIM + f];
        a2 += X[(size_t)j2 * FDIM + f];
        a3 += X[(size_t)j3 * FDIM + f];
    }
    for (; t < n; t++) {
        a0 += X[(size_t)s_idx[t] * FDIM + f];
    }
    g_S[(size_t)r * FDIM + f] = ((a0 + a1) + (a2 + a3));
}

// ---------------------------------------------------------------------------
// Kernel 2: out = (S @ W) / deg[row] + (rowcnt[row]/deg[row]) * b[col]
// Tiled SGEMM: BM=128, BN=64, BK=16, 256 threads, 8x4 per-thread tile.
// ---------------------------------------------------------------------------
#define BM 128
#define BN 64
#define BK 16

__global__ __launch_bounds__(256) void gemm_epilogue_kernel(
    const float* __restrict__ W,
    const float* __restrict__ bias,
    float* __restrict__ out)
{
    __shared__ float sA[BK][BM];   // S tile, transposed (k-major)
    __shared__ float sB[BK][BN];   // W tile

    const int tid = threadIdx.x;           // 0..255
    const int bm = blockIdx.y * BM;
    const int bn = blockIdx.x * BN;

    // A-load mapping: 128x16 = 2048 floats = 512 float4; 2 per thread
    const int ar = tid >> 2;               // 0..63
    const int ac = (tid & 3) * 4;          // 0,4,8,12
    // B-load mapping: 16x64 = 1024 floats = 256 float4; 1 per thread
    const int br = tid >> 4;               // 0..15
    const int bc = (tid & 15) * 4;         // 0..60

    const int ty = tid >> 4;               // 0..15 -> row group of 8
    const int tx = tid & 15;               // 0..15 -> col group of 4

    float acc[8][4];
#pragma unroll
    for (int i = 0; i < 8; i++)
#pragma unroll
        for (int j = 0; j < 4; j++) acc[i][j] = 0.0f;

    for (int k0 = 0; k0 < FDIM; k0 += BK) {
        // Load S tile (two 64-row halves per thread)
        float4 av0 = *reinterpret_cast<const float4*>(&g_S[(size_t)(bm + ar) * FDIM + k0 + ac]);
        float4 av1 = *reinterpret_cast<const float4*>(&g_S[(size_t)(bm + ar + 64) * FDIM + k0 + ac]);
        sA[ac + 0][ar] = av0.x; sA[ac + 1][ar] = av0.y;
        sA[ac + 2][ar] = av0.z; sA[ac + 3][ar] = av0.w;
        sA[ac + 0][ar + 64] = av1.x; sA[ac + 1][ar + 64] = av1.y;
        sA[ac + 2][ar + 64] = av1.z; sA[ac + 3][ar + 64] = av1.w;
        // Load W tile
        float4 bv = *reinterpret_cast<const float4*>(&W[(size_t)(k0 + br) * FDIM + bn + bc]);
        *reinterpret_cast<float4*>(&sB[br][bc]) = bv;
        __syncthreads();

#pragma unroll
        for (int k = 0; k < BK; k++) {
            float4 a0 = *reinterpret_cast<const float4*>(&sA[k][ty * 8]);
            float4 a1 = *reinterpret_cast<const float4*>(&sA[k][ty * 8 + 4]);
            float4 bb = *reinterpret_cast<const float4*>(&sB[k][tx * 4]);
            float a[8] = {a0.x, a0.y, a0.z, a0.w, a1.x, a1.y, a1.z, a1.w};
            float bvv[4] = {bb.x, bb.y, bb.z, bb.w};
#pragma unroll
            for (int i = 0; i < 8; i++)
#pragma unroll
                for (int j = 0; j < 4; j++)
                    acc[i][j] = fmaf(a[i], bvv[j], acc[i][j]);
        }
        __syncthreads();
    }

    // Epilogue: /deg[row] + (rowcnt[row]/deg[row]) * bias[col]
#pragma unroll
    for (int i = 0; i < 8; i++) {
        int row = bm + ty * 8 + i;
        float inv = 1.0f / g_deg[row];
        float bscale = g_rowcnt[row] * inv;
        float4 bo;
        int col = bn + tx * 4;
        float4 bsv = *reinterpret_cast<const float4*>(&bias[col]);
        bo.x = acc[i][0] * inv + bscale * bsv.x;
        bo.y = acc[i][1] * inv + bscale * bsv.y;
        bo.z = acc[i][2] * inv + bscale * bsv.z;
        bo.w = acc[i][3] * inv + bscale * bsv.w;
        *reinterpret_cast<float4*>(&out[(size_t)row * FDIM + col]) = bo;
    }
}

// ---------------------------------------------------------------------------
// Launch
// ---------------------------------------------------------------------------
extern "C" void kernel_launch(void* const* d_in, const int* in_sizes, int n_in,
                              void* d_out, int out_size) {
    const float* X   = (const float*)d_in[0];   // [8192, 512]
    const float* adj = (const float*)d_in[1];   // [8192, 8192]
    const float* W   = (const float*)d_in[2];   // [512, 512]
    const float* b   = (const float*)d_in[3];   // [512]
    float* out = (float*)d_out;                 // [8192, 512]

    zero_deg_kernel<<<(NROWS + 511) / 512, 512>>>();

    spmm_ax_kernel<<<NROWS, 512>>>(adj, X);

    dim3 grid2(FDIM / BN, NROWS / BM);   // (8, 64)
    gemm_epilogue_kernel<<<grid2, 256>>>(W, b, out);
}

// round 4
// speedup vs baseline: 1.0067x; 1.0067x over previous
#include <cuda_runtime.h>
#include <cuda_bf16.h>
#include <cstdint>

// Problem constants (fixed shapes for this problem instance)
#define NROWS 8192
#define FDIM  512

// Scratch: S = A @ X (16 MB), colsum (deg), rowsum (nonzeros per row)
__device__ float g_S[(size_t)NROWS * FDIM];
__device__ float g_deg[NROWS];      // column sums of binarized A
__device__ float g_rowcnt[NROWS];   // row sums of binarized A

// ---------------------------------------------------------------------------
// f32x2 packed math helpers (sm_100+): FFMA2 doubles fp32 FMA throughput.
// ---------------------------------------------------------------------------
__device__ __forceinline__ void fma_f32x2(unsigned long long& d,
                                          unsigned long long a,
                                          unsigned long long b) {
    asm("fma.rn.f32x2 %0, %1, %2, %0;" : "+l"(d) : "l"(a), "l"(b));
}
__device__ __forceinline__ unsigned long long pack_dup_f32(float a) {
    unsigned long long r;
    asm("mov.b64 %0, {%1, %1};" : "=l"(r) : "f"(a));
    return r;
}
__device__ __forceinline__ void unpack_f32x2(float& lo, float& hi,
                                             unsigned long long v) {
    asm("mov.b64 {%0, %1}, %2;" : "=f"(lo), "=f"(hi) : "l"(v));
}

// ---------------------------------------------------------------------------
// Kernel 0: zero deg (graph replays must redo this every launch)
// ---------------------------------------------------------------------------
__global__ void zero_deg_kernel() {
    int i = blockIdx.x * blockDim.x + threadIdx.x;
    if (i < NROWS) g_deg[i] = 0.0f;
}

// ---------------------------------------------------------------------------
// Kernel 1: one CTA (512 thr) per output row r.
//   Phase A: scan adj row r; each thread owns a CONTIGUOUS 16-element chunk
//            (4 float4). Count nonzeros, block-wide exclusive scan, write
//            indices into s_idx in globally sorted order (deterministic).
//            atomicAdd(+1) into g_deg[col] per nonzero (exact integer adds,
//            order-independent). rowcnt = total nonzeros -> g_rowcnt[r].
//   Phase B: thread tid owns feature f=tid; S[r][f] = sum over sorted list,
//            8 independent partials for memory-level parallelism.
// ---------------------------------------------------------------------------
__global__ __launch_bounds__(512) void spmm_ax_kernel(
    const float* __restrict__ adj,
    const float* __restrict__ X)
{
    __shared__ int s_idx[NROWS];     // 32 KB worst case
    __shared__ int s_warp[16];       // per-warp count totals
    __shared__ int s_total;

    const int r = blockIdx.x;
    const int tid = threadIdx.x;
    const int lane = tid & 31;
    const int wid = tid >> 5;

    // Phase A: each thread reads 4 consecutive float4 (64B contiguous)
    const float4* row4 = reinterpret_cast<const float4*>(adj + (size_t)r * NROWS);
    float4 v0 = row4[tid * 4 + 0];
    float4 v1 = row4[tid * 4 + 1];
    float4 v2 = row4[tid * 4 + 2];
    float4 v3 = row4[tid * 4 + 3];

    int c = 0;
    c += (v0.x != 0.0f) + (v0.y != 0.0f) + (v0.z != 0.0f) + (v0.w != 0.0f);
    c += (v1.x != 0.0f) + (v1.y != 0.0f) + (v1.z != 0.0f) + (v1.w != 0.0f);
    c += (v2.x != 0.0f) + (v2.y != 0.0f) + (v2.z != 0.0f) + (v2.w != 0.0f);
    c += (v3.x != 0.0f) + (v3.y != 0.0f) + (v3.z != 0.0f) + (v3.w != 0.0f);

    // Warp-level inclusive scan of counts
    int incl = c;
#pragma unroll
    for (int d = 1; d < 32; d <<= 1) {
        int t = __shfl_up_sync(0xFFFFFFFFu, incl, d);
        if (lane >= d) incl += t;
    }
    if (lane == 31) s_warp[wid] = incl;
    __syncthreads();
    if (wid == 0) {
        int wv = (lane < 16) ? s_warp[lane] : 0;
#pragma unroll
        for (int d = 1; d < 16; d <<= 1) {
            int t = __shfl_up_sync(0xFFFFFFFFu, wv, d);
            if (lane >= d) wv += t;
        }
        if (lane < 16) s_warp[lane] = wv;
        if (lane == 15) s_total = wv;
    }
    __syncthreads();

    int ofs = incl - c + (wid > 0 ? s_warp[wid - 1] : 0);

    // Write indices (sorted order since chunks are thread-contiguous),
    // and accumulate column sums.
    {
        int p = ofs;
        int base = tid * 16;
        if (v0.x != 0.0f) { s_idx[p++] = base + 0;  atomicAdd(&g_deg[base + 0], 1.0f); }
        if (v0.y != 0.0f) { s_idx[p++] = base + 1;  atomicAdd(&g_deg[base + 1], 1.0f); }
        if (v0.z != 0.0f) { s_idx[p++] = base + 2;  atomicAdd(&g_deg[base + 2], 1.0f); }
        if (v0.w != 0.0f) { s_idx[p++] = base + 3;  atomicAdd(&g_deg[base + 3], 1.0f); }
        if (v1.x != 0.0f) { s_idx[p++] = base + 4;  atomicAdd(&g_deg[base + 4], 1.0f); }
        if (v1.y != 0.0f) { s_idx[p++] = base + 5;  atomicAdd(&g_deg[base + 5], 1.0f); }
        if (v1.z != 0.0f) { s_idx[p++] = base + 6;  atomicAdd(&g_deg[base + 6], 1.0f); }
        if (v1.w != 0.0f) { s_idx[p++] = base + 7;  atomicAdd(&g_deg[base + 7], 1.0f); }
        if (v2.x != 0.0f) { s_idx[p++] = base + 8;  atomicAdd(&g_deg[base + 8], 1.0f); }
        if (v2.y != 0.0f) { s_idx[p++] = base + 9;  atomicAdd(&g_deg[base + 9], 1.0f); }
        if (v2.z != 0.0f) { s_idx[p++] = base + 10; atomicAdd(&g_deg[base + 10], 1.0f); }
        if (v2.w != 0.0f) { s_idx[p++] = base + 11; atomicAdd(&g_deg[base + 11], 1.0f); }
        if (v3.x != 0.0f) { s_idx[p++] = base + 12; atomicAdd(&g_deg[base + 12], 1.0f); }
        if (v3.y != 0.0f) { s_idx[p++] = base + 13; atomicAdd(&g_deg[base + 13], 1.0f); }
        if (v3.z != 0.0f) { s_idx[p++] = base + 14; atomicAdd(&g_deg[base + 14], 1.0f); }
        if (v3.w != 0.0f) { s_idx[p++] = base + 15; atomicAdd(&g_deg[base + 15], 1.0f); }
    }
    __syncthreads();

    const int n = s_total;
    if (tid == 0) g_rowcnt[r] = (float)n;

    // Phase B: gather-accumulate in fixed (sorted) order, 8 partials for MLP.
    const int f = tid;
    float a0 = 0.f, a1 = 0.f, a2 = 0.f, a3 = 0.f;
    float a4 = 0.f, a5 = 0.f, a6 = 0.f, a7 = 0.f;
    int t = 0;
    for (; t + 8 <= n; t += 8) {
        int j0 = s_idx[t + 0], j1 = s_idx[t + 1], j2 = s_idx[t + 2], j3 = s_idx[t + 3];
        int j4 = s_idx[t + 4], j5 = s_idx[t + 5], j6 = s_idx[t + 6], j7 = s_idx[t + 7];
        a0 += __ldg(&X[(size_t)j0 * FDIM + f]);
        a1 += __ldg(&X[(size_t)j1 * FDIM + f]);
        a2 += __ldg(&X[(size_t)j2 * FDIM + f]);
        a3 += __ldg(&X[(size_t)j3 * FDIM + f]);
        a4 += __ldg(&X[(size_t)j4 * FDIM + f]);
        a5 += __ldg(&X[(size_t)j5 * FDIM + f]);
        a6 += __ldg(&X[(size_t)j6 * FDIM + f]);
        a7 += __ldg(&X[(size_t)j7 * FDIM + f]);
    }
    for (; t < n; t++) {
        a0 += __ldg(&X[(size_t)s_idx[t] * FDIM + f]);
    }
    g_S[(size_t)r * FDIM + f] = ((a0 + a1) + (a2 + a3)) + ((a4 + a5) + (a6 + a7));
}

// ---------------------------------------------------------------------------
// Kernel 2: out = (S @ W) / deg[row] + (rowcnt[row]/deg[row]) * b[col]
// Tiled SGEMM with packed f32x2 FMA (FFMA2):
//   BM=128, BN=128, BK=16, 256 threads, 8x8 per-thread tile (8x4 f32x2 accs).
// ---------------------------------------------------------------------------
#define BM 128
#define BN 128
#define BK 16

__global__ __launch_bounds__(256) void gemm_epilogue_kernel(
    const float* __restrict__ W,
    const float* __restrict__ bias,
    float* __restrict__ out)
{
    __shared__ float sA[BK][BM];   // S tile, transposed (k-major)  8 KB
    __shared__ float sB[BK][BN];   // W tile                        8 KB

    const int tid = threadIdx.x;           // 0..255
    const int bm = blockIdx.y * BM;
    const int bn = blockIdx.x * BN;

    // A-load mapping: 128x16 = 2048 floats; 8 floats (2 float4) per thread
    const int ar = tid >> 1;               // 0..127
    const int ac = (tid & 1) * 8;          // 0 or 8
    // B-load mapping: 16x128 = 2048 floats; 8 floats per thread
    const int br = tid >> 4;               // 0..15
    const int bc = (tid & 15) * 8;         // 0..120

    const int ty = tid >> 4;               // 0..15 -> row group of 8
    const int tx = tid & 15;               // 0..15 -> col group of 8

    unsigned long long acc[8][4];          // 8 rows x 4 f32x2 pairs (8 cols)
#pragma unroll
    for (int i = 0; i < 8; i++)
#pragma unroll
        for (int j = 0; j < 4; j++) acc[i][j] = 0ULL;  // bit pattern of (0.f,0.f)

    for (int k0 = 0; k0 < FDIM; k0 += BK) {
        // Load S tile: thread loads 8 consecutive k-values of one row
        float4 av0 = *reinterpret_cast<const float4*>(&g_S[(size_t)(bm + ar) * FDIM + k0 + ac]);
        float4 av1 = *reinterpret_cast<const float4*>(&g_S[(size_t)(bm + ar) * FDIM + k0 + ac + 4]);
        sA[ac + 0][ar] = av0.x; sA[ac + 1][ar] = av0.y;
        sA[ac + 2][ar] = av0.z; sA[ac + 3][ar] = av0.w;
        sA[ac + 4][ar] = av1.x; sA[ac + 5][ar] = av1.y;
        sA[ac + 6][ar] = av1.z; sA[ac + 7][ar] = av1.w;
        // Load W tile
        float4 bv0 = *reinterpret_cast<const float4*>(&W[(size_t)(k0 + br) * FDIM + bn + bc]);
        float4 bv1 = *reinterpret_cast<const float4*>(&W[(size_t)(k0 + br) * FDIM + bn + bc + 4]);
        *reinterpret_cast<float4*>(&sB[br][bc]) = bv0;
        *reinterpret_cast<float4*>(&sB[br][bc + 4]) = bv1;
        __syncthreads();

#pragma unroll
        for (int k = 0; k < BK; k++) {
            float4 af0 = *reinterpret_cast<const float4*>(&sA[k][ty * 8]);
            float4 af1 = *reinterpret_cast<const float4*>(&sA[k][ty * 8 + 4]);
            const unsigned long long* bp =
                reinterpret_cast<const unsigned long long*>(&sB[k][tx * 8]);
            unsigned long long b2[4] = {bp[0], bp[1], bp[2], bp[3]};
            float av[8] = {af0.x, af0.y, af0.z, af0.w, af1.x, af1.y, af1.z, af1.w};
#pragma unroll
            for (int i = 0; i < 8; i++) {
                unsigned long long a2 = pack_dup_f32(av[i]);
#pragma unroll
                for (int j = 0; j < 4; j++)
                    fma_f32x2(acc[i][j], a2, b2[j]);
            }
        }
        __syncthreads();
    }

    // Epilogue: /deg[row] + (rowcnt[row]/deg[row]) * bias[col]
    const int colb = bn + tx * 8;
    float4 bsv0 = *reinterpret_cast<const float4*>(&bias[colb]);
    float4 bsv1 = *reinterpret_cast<const float4*>(&bias[colb + 4]);
    float bsa[8] = {bsv0.x, bsv0.y, bsv0.z, bsv0.w, bsv1.x, bsv1.y, bsv1.z, bsv1.w};

#pragma unroll
    for (int i = 0; i < 8; i++) {
        int row = bm + ty * 8 + i;
        float inv = 1.0f / g_deg[row];
        float bscale = g_rowcnt[row] * inv;
        float res[8];
#pragma unroll
        for (int j = 0; j < 4; j++) {
            float lo, hi;
            unpack_f32x2(lo, hi, acc[i][j]);
            res[2 * j + 0] = lo * inv + bscale * bsa[2 * j + 0];
            res[2 * j + 1] = hi * inv + bscale * bsa[2 * j + 1];
        }
        float4 o0 = {res[0], res[1], res[2], res[3]};
        float4 o1 = {res[4], res[5], res[6], res[7]};
        *reinterpret_cast<float4*>(&out[(size_t)row * FDIM + colb]) = o0;
        *reinterpret_cast<float4*>(&out[(size_t)row * FDIM + colb + 4]) = o1;
    }
}

// ---------------------------------------------------------------------------
// Launch
// ---------------------------------------------------------------------------
extern "C" void kernel_launch(void* const* d_in, const int* in_sizes, int n_in,
                              void* d_out, int out_size) {
    const float* X   = (const float*)d_in[0];   // [8192, 512]
    const float* adj = (const float*)d_in[1];   // [8192, 8192]
    const float* W   = (const float*)d_in[2];   // [512, 512]
    const float* b   = (const float*)d_in[3];   // [512]
    float* out = (float*)d_out;                 // [8192, 512]

    zero_deg_kernel<<<(NROWS + 511) / 512, 512>>>();

    spmm_ax_kernel<<<NROWS, 512>>>(adj, X);

    dim3 grid2(FDIM / BN, NROWS / BM);   // (4, 64)
    gemm_epilogue_kernel<<<grid2, 256>>>(W, b, out);
}